// round 16
// baseline (speedup 1.0000x reference)
#include <cuda_runtime.h>
#include <cuda_fp16.h>
#include <math.h>

#define NN   50000
#define EE   800000
#define FIN  256
#define HH   64
#define NHH  4
#define GDIM 256   // NH*H
#define SCAN_B 196 // ceil(50000/256)

// ---------------- device scratch (static, allowed) ----------------
__device__ int      g_flag;
__device__ int      g_src[EE];
__device__ int      g_dst[EE];
__device__ int      g_cnt[NN];
__device__ int      g_row[NN];
__device__ int      g_cursor[NN];
__device__ int      g_bsum[SCAN_B];
__device__ int      g_csr[EE];
__device__ float    g_dinv[NN];
__device__ __align__(16) __half g_t64[(size_t)NN * HH];   // fp16 dinv-scaled pre-agg
__device__ float    g_h[(size_t)NN * HH];
__device__ __align__(16) __half g_hph[(size_t)NN * GDIM];
__device__ float    g_gat[(size_t)NN * GDIM];             // fp32 (late-stage, keep exact)
__device__ float    g_as[NN * NHH];
__device__ float    g_ad[NN * NHH];

__device__ __forceinline__ void fma4(float* a, float x, float4 w) {
    a[0] = fmaf(x, w.x, a[0]);
    a[1] = fmaf(x, w.y, a[1]);
    a[2] = fmaf(x, w.z, a[2]);
    a[3] = fmaf(x, w.w, a[3]);
}

__device__ __forceinline__ unsigned to_tf32(float f) {
    unsigned u;
    asm("cvt.rna.tf32.f32 %0, %1;" : "=r"(u) : "f"(f));
    return u;
}

// ---------------- edge prep ----------------
__global__ void k_prep(const int* __restrict__ ei32) {
    int i = blockIdx.x * 256 + threadIdx.x;
    if (i < NN) g_cnt[i] = 0;
    if (blockIdx.x == 0) {
        __shared__ int bad;
        if (threadIdx.x == 0) bad = 0;
        __syncthreads();
        for (int t = threadIdx.x; t < 4096; t += 256)
            if (ei32[2 * t + 1] != 0) bad = 1;
        __syncthreads();
        if (threadIdx.x == 0) g_flag = bad ? 0 : 1;
    }
}

__global__ void k_convert(const int* __restrict__ p) {
    int i = blockIdx.x * blockDim.x + threadIdx.x;
    if (i >= EE) return;
    int s, d;
    if (g_flag) { s = p[2 * i]; d = p[2 * (EE + i)]; }
    else        { s = p[i];     d = p[EE + i]; }
    g_src[i] = s;
    g_dst[i] = d;
    atomicAdd(&g_cnt[d], 1);
}

__global__ void k_dinv() {
    int i = blockIdx.x * blockDim.x + threadIdx.x;
    if (i < NN) g_dinv[i] = rsqrtf((float)(g_cnt[i] + 1));
}

// ---------------- 2-level exclusive scan of g_cnt ----------------
__global__ void k_scan1() {
    __shared__ int sm[256];
    int tid = threadIdx.x;
    int i = blockIdx.x * 256 + tid;
    int v = (i < NN) ? g_cnt[i] : 0;
    sm[tid] = v;
    __syncthreads();
    for (int o = 1; o < 256; o <<= 1) {
        int t = (tid >= o) ? sm[tid - o] : 0;
        __syncthreads();
        sm[tid] += t;
        __syncthreads();
    }
    if (i < NN) g_row[i] = sm[tid] - v;
    if (tid == 255) g_bsum[blockIdx.x] = sm[255];
}

__global__ void k_scan2() {
    __shared__ int sm[256];
    int tid = threadIdx.x;
    int v = (tid < SCAN_B) ? g_bsum[tid] : 0;
    sm[tid] = v;
    __syncthreads();
    for (int o = 1; o < 256; o <<= 1) {
        int t = (tid >= o) ? sm[tid - o] : 0;
        __syncthreads();
        sm[tid] += t;
        __syncthreads();
    }
    if (tid < SCAN_B) g_bsum[tid] = sm[tid] - v;
}

__global__ void k_scan3() {
    int i = blockIdx.x * blockDim.x + threadIdx.x;
    if (i >= NN) return;
    int r = g_row[i] + g_bsum[i >> 8];
    g_row[i] = r;
    g_cursor[i] = r;
}

__global__ void k_scatter() {
    int i = blockIdx.x * blockDim.x + threadIdx.x;
    if (i >= EE) return;
    int d = g_dst[i];
    int pos = atomicAdd(&g_cursor[d], 1);
    g_csr[pos] = g_src[i];
}

// ---------------- gemm1: tf32 tensor-core, X[N,256]@W1[256,64] ----------
// block = 64 nodes, 8 warps. warp w: m-tile (w&3)*16, n-tiles (w>>2)*32 + t*8.
// xs [node][k] stride 68, ws [k][n] stride 72 — fragment loads conflict-free.
__global__ __launch_bounds__(256) void k_gemm1_tc(const float* __restrict__ X,
                                                  const float* __restrict__ W,
                                                  const float* __restrict__ dscale,
                                                  __half* __restrict__ Y) {
    __shared__ unsigned xs[64][68];
    __shared__ unsigned ws[64][72];
    int lane = threadIdx.x & 31;
    int w    = threadIdx.x >> 5;
    int m0   = (w & 3) * 16;
    int ng0  = (w >> 2) * 32;
    int n0   = blockIdx.x * 64;
    float c[4][4] = {};
    for (int kt = 0; kt < 256; kt += 64) {
        __syncthreads();
        for (int idx = threadIdx.x; idx < 64 * 64; idx += 256) {
            int r = idx >> 6, cc = idx & 63;
            int n = n0 + r;
            float xv = (n < NN) ? X[(size_t)n * 256 + kt + cc] : 0.f;
            xs[r][cc] = to_tf32(xv);
            ws[r][cc] = to_tf32(W[(size_t)(kt + r) * 64 + cc]);
        }
        __syncthreads();
#pragma unroll
        for (int k8 = 0; k8 < 64; k8 += 8) {
            int arow = m0 + (lane >> 2);
            int acol = k8 + (lane & 3);
            unsigned a0 = xs[arow][acol];
            unsigned a1 = xs[arow + 8][acol];
            unsigned a2 = xs[arow][acol + 4];
            unsigned a3 = xs[arow + 8][acol + 4];
#pragma unroll
            for (int t = 0; t < 4; t++) {
                int bcol = ng0 + t * 8 + (lane >> 2);
                int brow = k8 + (lane & 3);
                unsigned b0 = ws[brow][bcol];
                unsigned b1 = ws[brow + 4][bcol];
                asm volatile(
                    "mma.sync.aligned.m16n8k8.row.col.f32.tf32.tf32.f32 "
                    "{%0,%1,%2,%3}, {%4,%5,%6,%7}, {%8,%9}, {%0,%1,%2,%3};"
                    : "+f"(c[t][0]), "+f"(c[t][1]), "+f"(c[t][2]), "+f"(c[t][3])
                    : "r"(a0), "r"(a1), "r"(a2), "r"(a3), "r"(b0), "r"(b1));
            }
        }
    }
    // epilogue: c0,c1 -> row r0, cols 2q,2q+1; c2,c3 -> row r0+8 (q = lane&3)
    int r0 = n0 + m0 + (lane >> 2);
    int r1 = r0 + 8;
    float d0 = (r0 < NN) ? dscale[r0] : 0.f;
    float d1 = (r1 < NN) ? dscale[r1] : 0.f;
#pragma unroll
    for (int t = 0; t < 4; t++) {
        int col = ng0 + t * 8 + (lane & 3) * 2;
        if (r0 < NN)
            *(__half2*)(Y + (size_t)r0 * 64 + col) =
                __floats2half2_rn(c[t][0] * d0, c[t][1] * d0);
        if (r1 < NN)
            *(__half2*)(Y + (size_t)r1 * 64 + col) =
                __floats2half2_rn(c[t][2] * d1, c[t][3] * d1);
    }
}

// ---------------- scalar GEMM (DOUT=64), R12-proven (used for gemm2) ----
template <int DIN>
__global__ __launch_bounds__(256) void k_gemm_n64(const float* __restrict__ X,
                                                  const float* __restrict__ W,
                                                  const float* __restrict__ dscale,
                                                  __half* __restrict__ Y) {
    __shared__ float xsT[64][68];
    __shared__ float ws[64][64];
    int jg = threadIdx.x & 15;
    int tg = threadIdx.x >> 4;
    int n0 = blockIdx.x * 64;
    float acc[4][4] = {};
    for (int kt = 0; kt < DIN; kt += 64) {
        __syncthreads();
        for (int idx = threadIdx.x; idx < 64 * 64; idx += 256) {
            int r = idx >> 6, c = idx & 63;
            int n = n0 + r;
            xsT[c][r] = (n < NN) ? X[(size_t)n * DIN + kt + c] : 0.f;
            ws[r][c]  = W[(size_t)(kt + r) * 64 + c];
        }
        __syncthreads();
#pragma unroll 16
        for (int k = 0; k < 64; k++) {
            float4 w4 = *(const float4*)&ws[k][jg * 4];
            float4 xv = *(const float4*)&xsT[k][tg * 4];
            fma4(acc[0], xv.x, w4);
            fma4(acc[1], xv.y, w4);
            fma4(acc[2], xv.z, w4);
            fma4(acc[3], xv.w, w4);
        }
    }
#pragma unroll
    for (int tt = 0; tt < 4; tt++) {
        int n = n0 + tg * 4 + tt;
        if (n < NN) {
            float ds = dscale[n];
            union { __half2 h2[2]; uint2 u; } pk;
            pk.h2[0] = __floats2half2_rn(acc[tt][0] * ds, acc[tt][1] * ds);
            pk.h2[1] = __floats2half2_rn(acc[tt][2] * ds, acc[tt][3] * ds);
            *(uint2*)(Y + (size_t)n * 64 + jg * 4) = pk.u;
        }
    }
}

// ---------------- Wg GEMM (64->256) + att epilogue + fp16 store ----------
__global__ __launch_bounds__(256) void k_gemm_gat(const float* __restrict__ X,
                                                  const float* __restrict__ W,
                                                  const float* __restrict__ att_src,
                                                  const float* __restrict__ att_dst) {
    __shared__ float xsT[64][36];
    __shared__ float ws[32][256];
    int jg = threadIdx.x & 63;
    int tg = threadIdx.x >> 6;
    int lane = threadIdx.x & 31;
    int n0 = blockIdx.x * 32;
    for (int idx = threadIdx.x; idx < 32 * 64; idx += 256) {
        int r = idx >> 6, c = idx & 63;
        int n = n0 + r;
        xsT[c][r] = (n < NN) ? X[(size_t)n * 64 + c] : 0.f;
    }
    float acc[8][4] = {};
    for (int kt = 0; kt < 64; kt += 32) {
        __syncthreads();
        for (int idx = threadIdx.x; idx < 32 * 256; idx += 256) {
            int r = idx >> 8, c = idx & 255;
            ws[r][c] = W[(size_t)(kt + r) * 256 + c];
        }
        __syncthreads();
#pragma unroll 8
        for (int k = 0; k < 32; k++) {
            float4 w4 = *(const float4*)&ws[k][jg * 4];
            float4 x0 = *(const float4*)&xsT[kt + k][tg * 8];
            float4 x1 = *(const float4*)&xsT[kt + k][tg * 8 + 4];
            fma4(acc[0], x0.x, w4);
            fma4(acc[1], x0.y, w4);
            fma4(acc[2], x0.z, w4);
            fma4(acc[3], x0.w, w4);
            fma4(acc[4], x1.x, w4);
            fma4(acc[5], x1.y, w4);
            fma4(acc[6], x1.z, w4);
            fma4(acc[7], x1.w, w4);
        }
    }
    int j0 = jg * 4;
    int head = jg >> 4;
    float4 asw = *(const float4*)&att_src[j0];
    float4 adw = *(const float4*)&att_dst[j0];
#pragma unroll
    for (int tt = 0; tt < 8; tt++) {
        float vs = acc[tt][0] * asw.x + acc[tt][1] * asw.y +
                   acc[tt][2] * asw.z + acc[tt][3] * asw.w;
        float vd = acc[tt][0] * adw.x + acc[tt][1] * adw.y +
                   acc[tt][2] * adw.z + acc[tt][3] * adw.w;
        for (int o = 8; o; o >>= 1) {
            vs += __shfl_xor_sync(0xffffffffu, vs, o);
            vd += __shfl_xor_sync(0xffffffffu, vd, o);
        }
        if ((lane & 15) == 0) {
            int n = n0 + tg * 8 + tt;
            if (n < NN) {
                g_as[n * 4 + head] = vs;
                g_ad[n * 4 + head] = vd;
            }
        }
    }
#pragma unroll
    for (int tt = 0; tt < 8; tt++) {
        int n = n0 + tg * 8 + tt;
        if (n < NN) {
            union { __half2 h2[2]; uint2 u; } pk;
            pk.h2[0] = __floats2half2_rn(acc[tt][0], acc[tt][1]);
            pk.h2[1] = __floats2half2_rn(acc[tt][2], acc[tt][3]);
            *(uint2*)(g_hph + (size_t)n * GDIM + j0) = pk.u;
        }
    }
}

// ---------------- head GEMM (256->64) + relu + Wf2 dot -> out ------------
__global__ __launch_bounds__(256) void k_gemm_head(const float* __restrict__ X,
                                                   const float* __restrict__ W,
                                                   const float* __restrict__ bf1,
                                                   const float* __restrict__ wf2,
                                                   const float* __restrict__ bf2,
                                                   float* __restrict__ out) {
    __shared__ float xsT[64][68];
    __shared__ float ws[64][64];
    int jg = threadIdx.x & 15;
    int tg = threadIdx.x >> 4;
    int lane = threadIdx.x & 31;
    int n0 = blockIdx.x * 64;
    float acc[4][4] = {};
    for (int kt = 0; kt < 256; kt += 64) {
        __syncthreads();
        for (int idx = threadIdx.x; idx < 64 * 64; idx += 256) {
            int r = idx >> 6, c = idx & 63;
            int n = n0 + r;
            xsT[c][r] = (n < NN) ? X[(size_t)n * 256 + kt + c] : 0.f;
            ws[r][c]  = W[(size_t)(kt + r) * 64 + c];
        }
        __syncthreads();
#pragma unroll 16
        for (int k = 0; k < 64; k++) {
            float4 w4 = *(const float4*)&ws[k][jg * 4];
            float4 xv = *(const float4*)&xsT[k][tg * 4];
            fma4(acc[0], xv.x, w4);
            fma4(acc[1], xv.y, w4);
            fma4(acc[2], xv.z, w4);
            fma4(acc[3], xv.w, w4);
        }
    }
    int j0 = jg * 4;
    float4 b4 = *(const float4*)&bf1[j0];
    float4 w2 = *(const float4*)&wf2[j0];
#pragma unroll
    for (int tt = 0; tt < 4; tt++) {
        float v = fmaxf(acc[tt][0] + b4.x, 0.f) * w2.x +
                  fmaxf(acc[tt][1] + b4.y, 0.f) * w2.y +
                  fmaxf(acc[tt][2] + b4.z, 0.f) * w2.z +
                  fmaxf(acc[tt][3] + b4.w, 0.f) * w2.w;
        for (int o = 8; o; o >>= 1)
            v += __shfl_xor_sync(0xffffffffu, v, o);
        if ((lane & 15) == 0) {
            int n = n0 + tg * 4 + tt;
            if (n < NN) out[n] = v + bf2[0];
        }
    }
}

// ---------------- GCN aggregation (CSR, warp/node, prescaled fp16) -------
__global__ __launch_bounds__(256) void k_gcn_csr(const __half* __restrict__ hin,
                                                 const float* __restrict__ b,
                                                 float* __restrict__ out) {
    int wid = threadIdx.x >> 5, lane = threadIdx.x & 31;
    int d = blockIdx.x * 8 + wid;
    if (d >= NN) return;
    int row0 = g_row[d];
    int row1 = row0 + g_cnt[d];
    float dd = g_dinv[d];
    float ax = 0.f, ay = 0.f;
    for (int base = row0; base < row1; base += 32) {
        int e = base + lane;
        int sl = (e < row1) ? g_csr[e] : 0;
        int m = min(32, row1 - base);
        int i = 0;
        for (; i + 3 < m; i += 4) {
            int s0 = __shfl_sync(0xffffffffu, sl, i);
            int s1 = __shfl_sync(0xffffffffu, sl, i + 1);
            int s2 = __shfl_sync(0xffffffffu, sl, i + 2);
            int s3 = __shfl_sync(0xffffffffu, sl, i + 3);
            float2 v0 = __half22float2(*(const __half2*)(hin + (size_t)s0 * HH + 2 * lane));
            float2 v1 = __half22float2(*(const __half2*)(hin + (size_t)s1 * HH + 2 * lane));
            float2 v2 = __half22float2(*(const __half2*)(hin + (size_t)s2 * HH + 2 * lane));
            float2 v3 = __half22float2(*(const __half2*)(hin + (size_t)s3 * HH + 2 * lane));
            ax += (v0.x + v1.x) + (v2.x + v3.x);
            ay += (v0.y + v1.y) + (v2.y + v3.y);
        }
        for (; i < m; i++) {
            int s = __shfl_sync(0xffffffffu, sl, i);
            float2 v = __half22float2(*(const __half2*)(hin + (size_t)s * HH + 2 * lane));
            ax += v.x;
            ay += v.y;
        }
    }
    {
        float2 v = __half22float2(*(const __half2*)(hin + (size_t)d * HH + 2 * lane));
        ax += v.x;
        ay += v.y;
    }
    float2 bb = ((const float2*)b)[lane];
    float2 o;
    o.x = fmaxf(fmaf(ax, dd, bb.x), 0.f);
    o.y = fmaxf(fmaf(ay, dd, bb.y), 0.f);
    ((float2*)(out + (size_t)d * HH))[lane] = o;
}

__device__ __forceinline__ float lrelu(float a) {
    return a > 0.f ? a : 0.2f * a;
}
__device__ __forceinline__ float sel4(int h, float a, float b, float c, float d) {
    return h == 0 ? a : (h == 1 ? b : (h == 2 ? c : d));
}

// ---------------- fused GAT (CSR, warp/node, no-max softmax) -------------
__global__ __launch_bounds__(256) void k_gat_csr(const float* __restrict__ bg,
                                                 float* __restrict__ outg) {
    __shared__ int   ssm[8][32];
    __shared__ float wsm[8][32][4];
    int wid = threadIdx.x >> 5, lane = threadIdx.x & 31;
    int d = blockIdx.x * 8 + wid;
    if (d >= NN) return;
    int row0 = g_row[d];
    int row1 = row0 + g_cnt[d];
    int head = lane >> 3;

    float ad0 = g_ad[d * 4 + 0], ad1 = g_ad[d * 4 + 1];
    float ad2 = g_ad[d * 4 + 2], ad3 = g_ad[d * 4 + 3];

    float a0 = 0.f, a1 = 0.f, a2 = 0.f, a3 = 0.f;
    float a4 = 0.f, a5 = 0.f, a6 = 0.f, a7 = 0.f;
    float dn0 = 0.f, dn1 = 0.f, dn2 = 0.f, dn3 = 0.f;

    for (int base = row0; base < row1; base += 32) {
        int e = base + lane;
        float w0 = 0.f, w1 = 0.f, w2 = 0.f, w3 = 0.f;
        if (e < row1) {
            int s = g_csr[e];
            ssm[wid][lane] = s;
            const float* as = g_as + s * 4;
            w0 = __expf(lrelu(as[0] + ad0));
            w1 = __expf(lrelu(as[1] + ad1));
            w2 = __expf(lrelu(as[2] + ad2));
            w3 = __expf(lrelu(as[3] + ad3));
            wsm[wid][lane][0] = w0;
            wsm[wid][lane][1] = w1;
            wsm[wid][lane][2] = w2;
            wsm[wid][lane][3] = w3;
        }
        dn0 += w0; dn1 += w1; dn2 += w2; dn3 += w3;
        __syncwarp();
        int m = min(32, row1 - base);
        for (int i = 0; i < m; i++) {
            int   s  = ssm[wid][i];
            float wt = wsm[wid][i][head];
            uint4 p = *(const uint4*)(g_hph + (size_t)s * GDIM + lane * 8);
            float2 f0 = __half22float2(*(__half2*)&p.x);
            float2 f1 = __half22float2(*(__half2*)&p.y);
            float2 f2 = __half22float2(*(__half2*)&p.z);
            float2 f3 = __half22float2(*(__half2*)&p.w);
            a0 = fmaf(f0.x, wt, a0); a1 = fmaf(f0.y, wt, a1);
            a2 = fmaf(f1.x, wt, a2); a3 = fmaf(f1.y, wt, a3);
            a4 = fmaf(f2.x, wt, a4); a5 = fmaf(f2.y, wt, a5);
            a6 = fmaf(f3.x, wt, a6); a7 = fmaf(f3.y, wt, a7);
        }
        __syncwarp();
    }
    for (int o = 16; o; o >>= 1) {
        dn0 += __shfl_xor_sync(0xffffffffu, dn0, o);
        dn1 += __shfl_xor_sync(0xffffffffu, dn1, o);
        dn2 += __shfl_xor_sync(0xffffffffu, dn2, o);
        dn3 += __shfl_xor_sync(0xffffffffu, dn3, o);
    }
    float adh = sel4(head, ad0, ad1, ad2, ad3);
    float dnh = sel4(head, dn0, dn1, dn2, dn3);

    float wslf = __expf(lrelu(g_as[d * 4 + head] + adh));
    dnh += wslf;
    {
        uint4 p = *(const uint4*)(g_hph + (size_t)d * GDIM + lane * 8);
        float2 f0 = __half22float2(*(__half2*)&p.x);
        float2 f1 = __half22float2(*(__half2*)&p.y);
        float2 f2 = __half22float2(*(__half2*)&p.z);
        float2 f3 = __half22float2(*(__half2*)&p.w);
        a0 = fmaf(f0.x, wslf, a0); a1 = fmaf(f0.y, wslf, a1);
        a2 = fmaf(f1.x, wslf, a2); a3 = fmaf(f1.y, wslf, a3);
        a4 = fmaf(f2.x, wslf, a4); a5 = fmaf(f2.y, wslf, a5);
        a6 = fmaf(f3.x, wslf, a6); a7 = fmaf(f3.y, wslf, a7);
    }
    float inv = 1.f / dnh;
    const float4* bg4 = (const float4*)(bg + lane * 8);
    float4 b0 = bg4[0], b1 = bg4[1];
    float4 o0 = make_float4(a0 * inv + b0.x, a1 * inv + b0.y,
                            a2 * inv + b0.z, a3 * inv + b0.w);
    float4 o1 = make_float4(a4 * inv + b1.x, a5 * inv + b1.y,
                            a6 * inv + b1.z, a7 * inv + b1.w);
    float4* out4 = (float4*)(outg + (size_t)d * GDIM + lane * 8);
    out4[0] = o0;
    out4[1] = o1;
}

static inline int cdiv(long long a, int b) { return (int)((a + b - 1) / b); }

static void* sym_addr(const void* sym) {
    void* p = nullptr;
    cudaGetSymbolAddress(&p, sym);
    return p;
}

extern "C" void kernel_launch(void* const* d_in, const int* in_sizes, int n_in,
                              void* d_out, int out_size) {
    const float* x       = (const float*)d_in[0];
    const int*   ei      = (const int*)  d_in[1];
    const float* W1      = (const float*)d_in[2];
    const float* b1      = (const float*)d_in[3];
    const float* W2      = (const float*)d_in[4];
    const float* b2      = (const float*)d_in[5];
    const float* Wg      = (const float*)d_in[6];
    const float* att_src = (const float*)d_in[7];
    const float* att_dst = (const float*)d_in[8];
    const float* bg      = (const float*)d_in[9];
    const float* Wf1     = (const float*)d_in[10];
    const float* bf1     = (const float*)d_in[11];
    const float* Wf2     = (const float*)d_in[12];
    const float* bf2     = (const float*)d_in[13];
    float*       out     = (float*)d_out;

    static __half* p_t64  = nullptr;
    static float*  p_h    = nullptr;
    static float*  p_gat  = nullptr;
    static float*  p_dinv = nullptr;
    if (!p_t64) {
        p_t64  = (__half*)sym_addr(g_t64);
        p_h    = (float*) sym_addr(g_h);
        p_gat  = (float*) sym_addr(g_gat);
        p_dinv = (float*) sym_addr(g_dinv);
    }

    const int B = 256;

    // ---- CSR build (tf32 gemm1 slotted at launch index 3 for profiling) ----
    k_prep<<<cdiv(NN, B), B>>>(ei);
    k_convert<<<cdiv(EE, B), B>>>(ei);
    k_dinv<<<cdiv(NN, B), B>>>();
    k_gemm1_tc<<<cdiv(NN, 64), B>>>(x, W1, p_dinv, p_t64);      // index 3
    k_scan1<<<SCAN_B, B>>>();
    k_scan2<<<1, B>>>();
    k_scan3<<<cdiv(NN, B), B>>>();
    k_scatter<<<cdiv(EE, B), B>>>();

    // ---- GCN layer 1 ----
    k_gcn_csr<<<cdiv(NN, 8), B>>>(p_t64, b1, p_h);

    // ---- GCN layer 2 ----
    k_gemm_n64<HH><<<cdiv(NN, 64), B>>>(p_h, W2, p_dinv, p_t64);
    k_gcn_csr<<<cdiv(NN, 8), B>>>(p_t64, b2, p_h);

    // ---- GAT ----
    k_gemm_gat<<<cdiv(NN, 32), B>>>(p_h, Wg, att_src, att_dst);
    k_gat_csr<<<cdiv(NN, 8), B>>>(bg, p_gat);

    // ---- FF head (fused Wf1+relu+Wf2) ----
    k_gemm_head<<<cdiv(NN, 64), B>>>(p_gat, Wf1, bf1, Wf2, bf2, out);

    (void)in_sizes; (void)n_in; (void)out_size;
}

// round 17
// speedup vs baseline: 1.5058x; 1.5058x over previous
#include <cuda_runtime.h>
#include <cuda_fp16.h>
#include <math.h>

#define NN   50000
#define EE   800000
#define FIN  256
#define HH   64
#define NHH  4
#define GDIM 256   // NH*H
#define SCAN_B 196 // ceil(50000/256)

// ---------------- device scratch (static, allowed) ----------------
__device__ int      g_flag;
__device__ int      g_src[EE];
__device__ int      g_dst[EE];
__device__ int      g_cnt[NN];
__device__ int      g_row[NN];
__device__ int      g_cursor[NN];
__device__ int      g_bsum[SCAN_B];
__device__ int      g_csr[EE];
__device__ float    g_dinv[NN];
__device__ __align__(16) __half g_t64[(size_t)NN * HH];  // fp16 dinv-scaled pre-agg
__device__ __align__(16) __half g_hh[(size_t)NN * HH];   // fp16 GCN outputs (early-stage)
__device__ __align__(16) __half g_hph[(size_t)NN * GDIM];
__device__ float    g_gat[(size_t)NN * GDIM];            // fp32 (late-stage, keep exact)
__device__ float    g_as[NN * NHH];
__device__ float    g_ad[NN * NHH];

__device__ __forceinline__ void fma4(float* a, float x, float4 w) {
    a[0] = fmaf(x, w.x, a[0]);
    a[1] = fmaf(x, w.y, a[1]);
    a[2] = fmaf(x, w.z, a[2]);
    a[3] = fmaf(x, w.w, a[3]);
}

// ---------------- edge prep ----------------
__global__ void k_prep(const int* __restrict__ ei32) {
    int i = blockIdx.x * 256 + threadIdx.x;
    if (i < NN) g_cnt[i] = 0;
    if (blockIdx.x == 0) {
        __shared__ int bad;
        if (threadIdx.x == 0) bad = 0;
        __syncthreads();
        for (int t = threadIdx.x; t < 4096; t += 256)
            if (ei32[2 * t + 1] != 0) bad = 1;
        __syncthreads();
        if (threadIdx.x == 0) g_flag = bad ? 0 : 1;
    }
}

__global__ void k_convert(const int* __restrict__ p) {
    int i = blockIdx.x * blockDim.x + threadIdx.x;
    if (i >= EE) return;
    int s, d;
    if (g_flag) { s = p[2 * i]; d = p[2 * (EE + i)]; }
    else        { s = p[i];     d = p[EE + i]; }
    g_src[i] = s;
    g_dst[i] = d;
    atomicAdd(&g_cnt[d], 1);
}

__global__ void k_dinv() {
    int i = blockIdx.x * blockDim.x + threadIdx.x;
    if (i < NN) g_dinv[i] = rsqrtf((float)(g_cnt[i] + 1));
}

// ---------------- 2-level exclusive scan of g_cnt ----------------
__global__ void k_scan1() {
    __shared__ int sm[256];
    int tid = threadIdx.x;
    int i = blockIdx.x * 256 + tid;
    int v = (i < NN) ? g_cnt[i] : 0;
    sm[tid] = v;
    __syncthreads();
    for (int o = 1; o < 256; o <<= 1) {
        int t = (tid >= o) ? sm[tid - o] : 0;
        __syncthreads();
        sm[tid] += t;
        __syncthreads();
    }
    if (i < NN) g_row[i] = sm[tid] - v;
    if (tid == 255) g_bsum[blockIdx.x] = sm[255];
}

__global__ void k_scan2() {
    __shared__ int sm[256];
    int tid = threadIdx.x;
    int v = (tid < SCAN_B) ? g_bsum[tid] : 0;
    sm[tid] = v;
    __syncthreads();
    for (int o = 1; o < 256; o <<= 1) {
        int t = (tid >= o) ? sm[tid - o] : 0;
        __syncthreads();
        sm[tid] += t;
        __syncthreads();
    }
    if (tid < SCAN_B) g_bsum[tid] = sm[tid] - v;
}

__global__ void k_scan3() {
    int i = blockIdx.x * blockDim.x + threadIdx.x;
    if (i >= NN) return;
    int r = g_row[i] + g_bsum[i >> 8];
    g_row[i] = r;
    g_cursor[i] = r;
}

__global__ void k_scatter() {
    int i = blockIdx.x * blockDim.x + threadIdx.x;
    if (i >= EE) return;
    int d = g_dst[i];
    int pos = atomicAdd(&g_cursor[d], 1);
    g_csr[pos] = g_src[i];
}

// ---------------- gemm1 (fp32 in): k-major tile, 4 nodes x 4 cols -------
__global__ __launch_bounds__(256) void k_gemm1(const float* __restrict__ X,
                                               const float* __restrict__ W,
                                               const float* __restrict__ dscale,
                                               __half* __restrict__ Y) {
    __shared__ float xsT[64][68];
    __shared__ float ws[64][64];
    int jg = threadIdx.x & 15;
    int tg = threadIdx.x >> 4;
    int n0 = blockIdx.x * 64;
    float acc[4][4] = {};
    for (int kt = 0; kt < FIN; kt += 64) {
        __syncthreads();
        for (int idx = threadIdx.x; idx < 64 * 64; idx += 256) {
            int r = idx >> 6, c = idx & 63;
            int n = n0 + r;
            xsT[c][r] = (n < NN) ? X[(size_t)n * FIN + kt + c] : 0.f;
            ws[r][c]  = W[(size_t)(kt + r) * 64 + c];
        }
        __syncthreads();
#pragma unroll 16
        for (int k = 0; k < 64; k++) {
            float4 w4 = *(const float4*)&ws[k][jg * 4];
            float4 xv = *(const float4*)&xsT[k][tg * 4];
            fma4(acc[0], xv.x, w4);
            fma4(acc[1], xv.y, w4);
            fma4(acc[2], xv.z, w4);
            fma4(acc[3], xv.w, w4);
        }
    }
#pragma unroll
    for (int tt = 0; tt < 4; tt++) {
        int n = n0 + tg * 4 + tt;
        if (n < NN) {
            float ds = dscale[n];
            union { __half2 h2[2]; uint2 u; } pk;
            pk.h2[0] = __floats2half2_rn(acc[tt][0] * ds, acc[tt][1] * ds);
            pk.h2[1] = __floats2half2_rn(acc[tt][2] * ds, acc[tt][3] * ds);
            *(uint2*)(Y + (size_t)n * 64 + jg * 4) = pk.u;
        }
    }
}

// ---------------- gemm2 (fp16 in, 64->64): same tile, half2 widen -------
__global__ __launch_bounds__(256) void k_gemm2(const __half* __restrict__ X,
                                               const float* __restrict__ W,
                                               const float* __restrict__ dscale,
                                               __half* __restrict__ Y) {
    __shared__ float xsT[64][68];
    __shared__ float ws[64][64];
    int jg = threadIdx.x & 15;
    int tg = threadIdx.x >> 4;
    int n0 = blockIdx.x * 64;
    float acc[4][4] = {};
    __syncthreads();
    for (int idx = threadIdx.x; idx < 64 * 32; idx += 256) {
        int r = idx >> 5, c2 = idx & 31;
        int n = n0 + r;
        float2 v = make_float2(0.f, 0.f);
        if (n < NN)
            v = __half22float2(((const __half2*)(X + (size_t)n * 64))[c2]);
        xsT[2 * c2][r]     = v.x;
        xsT[2 * c2 + 1][r] = v.y;
    }
    for (int idx = threadIdx.x; idx < 64 * 64; idx += 256) {
        int r = idx >> 6, c = idx & 63;
        ws[r][c] = W[(size_t)r * 64 + c];
    }
    __syncthreads();
#pragma unroll 16
    for (int k = 0; k < 64; k++) {
        float4 w4 = *(const float4*)&ws[k][jg * 4];
        float4 xv = *(const float4*)&xsT[k][tg * 4];
        fma4(acc[0], xv.x, w4);
        fma4(acc[1], xv.y, w4);
        fma4(acc[2], xv.z, w4);
        fma4(acc[3], xv.w, w4);
    }
#pragma unroll
    for (int tt = 0; tt < 4; tt++) {
        int n = n0 + tg * 4 + tt;
        if (n < NN) {
            float ds = dscale[n];
            union { __half2 h2[2]; uint2 u; } pk;
            pk.h2[0] = __floats2half2_rn(acc[tt][0] * ds, acc[tt][1] * ds);
            pk.h2[1] = __floats2half2_rn(acc[tt][2] * ds, acc[tt][3] * ds);
            *(uint2*)(Y + (size_t)n * 64 + jg * 4) = pk.u;
        }
    }
}

// ---------------- Wg GEMM (fp16 in, 64->256) + att epilogue --------------
__global__ __launch_bounds__(256) void k_gemm_gat(const __half* __restrict__ X,
                                                  const float* __restrict__ W,
                                                  const float* __restrict__ att_src,
                                                  const float* __restrict__ att_dst) {
    __shared__ float xsT[64][36];
    __shared__ float ws[32][256];
    int jg = threadIdx.x & 63;
    int tg = threadIdx.x >> 6;
    int lane = threadIdx.x & 31;
    int n0 = blockIdx.x * 32;
    for (int idx = threadIdx.x; idx < 32 * 32; idx += 256) {
        int r = idx >> 5, c2 = idx & 31;
        int n = n0 + r;
        float2 v = make_float2(0.f, 0.f);
        if (n < NN)
            v = __half22float2(((const __half2*)(X + (size_t)n * 64))[c2]);
        xsT[2 * c2][r]     = v.x;
        xsT[2 * c2 + 1][r] = v.y;
    }
    float acc[8][4] = {};
    for (int kt = 0; kt < 64; kt += 32) {
        __syncthreads();
        for (int idx = threadIdx.x; idx < 32 * 256; idx += 256) {
            int r = idx >> 8, c = idx & 255;
            ws[r][c] = W[(size_t)(kt + r) * 256 + c];
        }
        __syncthreads();
#pragma unroll 8
        for (int k = 0; k < 32; k++) {
            float4 w4 = *(const float4*)&ws[k][jg * 4];
            float4 x0 = *(const float4*)&xsT[kt + k][tg * 8];
            float4 x1 = *(const float4*)&xsT[kt + k][tg * 8 + 4];
            fma4(acc[0], x0.x, w4);
            fma4(acc[1], x0.y, w4);
            fma4(acc[2], x0.z, w4);
            fma4(acc[3], x0.w, w4);
            fma4(acc[4], x1.x, w4);
            fma4(acc[5], x1.y, w4);
            fma4(acc[6], x1.z, w4);
            fma4(acc[7], x1.w, w4);
        }
    }
    // ---- attention-logit epilogue ----
    int j0 = jg * 4;
    int head = jg >> 4;
    float4 asw = *(const float4*)&att_src[j0];
    float4 adw = *(const float4*)&att_dst[j0];
#pragma unroll
    for (int tt = 0; tt < 8; tt++) {
        float vs = acc[tt][0] * asw.x + acc[tt][1] * asw.y +
                   acc[tt][2] * asw.z + acc[tt][3] * asw.w;
        float vd = acc[tt][0] * adw.x + acc[tt][1] * adw.y +
                   acc[tt][2] * adw.z + acc[tt][3] * adw.w;
        for (int o = 8; o; o >>= 1) {
            vs += __shfl_xor_sync(0xffffffffu, vs, o);
            vd += __shfl_xor_sync(0xffffffffu, vd, o);
        }
        if ((lane & 15) == 0) {
            int n = n0 + tg * 8 + tt;
            if (n < NN) {
                g_as[n * 4 + head] = vs;
                g_ad[n * 4 + head] = vd;
            }
        }
    }
    // ---- fp16 hp store ----
#pragma unroll
    for (int tt = 0; tt < 8; tt++) {
        int n = n0 + tg * 8 + tt;
        if (n < NN) {
            union { __half2 h2[2]; uint2 u; } pk;
            pk.h2[0] = __floats2half2_rn(acc[tt][0], acc[tt][1]);
            pk.h2[1] = __floats2half2_rn(acc[tt][2], acc[tt][3]);
            *(uint2*)(g_hph + (size_t)n * GDIM + j0) = pk.u;
        }
    }
}

// ---------------- head GEMM (fp32 in, 256->64) + relu + Wf2 dot ----------
__global__ __launch_bounds__(256) void k_gemm_head(const float* __restrict__ X,
                                                   const float* __restrict__ W,
                                                   const float* __restrict__ bf1,
                                                   const float* __restrict__ wf2,
                                                   const float* __restrict__ bf2,
                                                   float* __restrict__ out) {
    __shared__ float xsT[64][68];
    __shared__ float ws[64][64];
    int jg = threadIdx.x & 15;
    int tg = threadIdx.x >> 4;
    int lane = threadIdx.x & 31;
    int n0 = blockIdx.x * 64;
    float acc[4][4] = {};
    for (int kt = 0; kt < 256; kt += 64) {
        __syncthreads();
        for (int idx = threadIdx.x; idx < 64 * 64; idx += 256) {
            int r = idx >> 6, c = idx & 63;
            int n = n0 + r;
            xsT[c][r] = (n < NN) ? X[(size_t)n * 256 + kt + c] : 0.f;
            ws[r][c]  = W[(size_t)(kt + r) * 64 + c];
        }
        __syncthreads();
#pragma unroll 16
        for (int k = 0; k < 64; k++) {
            float4 w4 = *(const float4*)&ws[k][jg * 4];
            float4 xv = *(const float4*)&xsT[k][tg * 4];
            fma4(acc[0], xv.x, w4);
            fma4(acc[1], xv.y, w4);
            fma4(acc[2], xv.z, w4);
            fma4(acc[3], xv.w, w4);
        }
    }
    int j0 = jg * 4;
    float4 b4 = *(const float4*)&bf1[j0];
    float4 w2 = *(const float4*)&wf2[j0];
#pragma unroll
    for (int tt = 0; tt < 4; tt++) {
        float v = fmaxf(acc[tt][0] + b4.x, 0.f) * w2.x +
                  fmaxf(acc[tt][1] + b4.y, 0.f) * w2.y +
                  fmaxf(acc[tt][2] + b4.z, 0.f) * w2.z +
                  fmaxf(acc[tt][3] + b4.w, 0.f) * w2.w;
        for (int o = 8; o; o >>= 1)
            v += __shfl_xor_sync(0xffffffffu, v, o);
        if ((lane & 15) == 0) {
            int n = n0 + tg * 4 + tt;
            if (n < NN) out[n] = v + bf2[0];
        }
    }
}

// ---------------- GCN aggregation (CSR, warp/node, fp16 in+out) ----------
// hin rows prescaled by dinv[src]; out = relu(dd*(Σ t[s] + t[d]) + b), fp16.
__global__ __launch_bounds__(256) void k_gcn_csr(const __half* __restrict__ hin,
                                                 const float* __restrict__ b,
                                                 __half* __restrict__ out) {
    int wid = threadIdx.x >> 5, lane = threadIdx.x & 31;
    int d = blockIdx.x * 8 + wid;
    if (d >= NN) return;
    int row0 = g_row[d];
    int row1 = row0 + g_cnt[d];
    float dd = g_dinv[d];
    float ax = 0.f, ay = 0.f;
    for (int base = row0; base < row1; base += 32) {
        int e = base + lane;
        int sl = (e < row1) ? g_csr[e] : 0;
        int m = min(32, row1 - base);
        int i = 0;
        for (; i + 3 < m; i += 4) {
            int s0 = __shfl_sync(0xffffffffu, sl, i);
            int s1 = __shfl_sync(0xffffffffu, sl, i + 1);
            int s2 = __shfl_sync(0xffffffffu, sl, i + 2);
            int s3 = __shfl_sync(0xffffffffu, sl, i + 3);
            float2 v0 = __half22float2(*(const __half2*)(hin + (size_t)s0 * HH + 2 * lane));
            float2 v1 = __half22float2(*(const __half2*)(hin + (size_t)s1 * HH + 2 * lane));
            float2 v2 = __half22float2(*(const __half2*)(hin + (size_t)s2 * HH + 2 * lane));
            float2 v3 = __half22float2(*(const __half2*)(hin + (size_t)s3 * HH + 2 * lane));
            ax += (v0.x + v1.x) + (v2.x + v3.x);
            ay += (v0.y + v1.y) + (v2.y + v3.y);
        }
        for (; i < m; i++) {
            int s = __shfl_sync(0xffffffffu, sl, i);
            float2 v = __half22float2(*(const __half2*)(hin + (size_t)s * HH + 2 * lane));
            ax += v.x;
            ay += v.y;
        }
    }
    {   // self loop
        float2 v = __half22float2(*(const __half2*)(hin + (size_t)d * HH + 2 * lane));
        ax += v.x;
        ay += v.y;
    }
    float2 bb = ((const float2*)b)[lane];
    float ox = fmaxf(fmaf(ax, dd, bb.x), 0.f);
    float oy = fmaxf(fmaf(ay, dd, bb.y), 0.f);
    *(__half2*)(out + (size_t)d * HH + 2 * lane) = __floats2half2_rn(ox, oy);
}

__device__ __forceinline__ float lrelu(float a) {
    return a > 0.f ? a : 0.2f * a;
}
__device__ __forceinline__ float sel4(int h, float a, float b, float c, float d) {
    return h == 0 ? a : (h == 1 ? b : (h == 2 ? c : d));
}

// ---------------- fused GAT (CSR, warp/node, no-max softmax) -------------
__global__ __launch_bounds__(256) void k_gat_csr(const float* __restrict__ bg,
                                                 float* __restrict__ outg) {
    __shared__ int   ssm[8][32];
    __shared__ float wsm[8][32][4];
    int wid = threadIdx.x >> 5, lane = threadIdx.x & 31;
    int d = blockIdx.x * 8 + wid;
    if (d >= NN) return;
    int row0 = g_row[d];
    int row1 = row0 + g_cnt[d];
    int head = lane >> 3;

    float ad0 = g_ad[d * 4 + 0], ad1 = g_ad[d * 4 + 1];
    float ad2 = g_ad[d * 4 + 2], ad3 = g_ad[d * 4 + 3];

    float a0 = 0.f, a1 = 0.f, a2 = 0.f, a3 = 0.f;
    float a4 = 0.f, a5 = 0.f, a6 = 0.f, a7 = 0.f;
    float dn0 = 0.f, dn1 = 0.f, dn2 = 0.f, dn3 = 0.f;

    for (int base = row0; base < row1; base += 32) {
        int e = base + lane;
        float w0 = 0.f, w1 = 0.f, w2 = 0.f, w3 = 0.f;
        if (e < row1) {
            int s = g_csr[e];
            ssm[wid][lane] = s;
            const float* as = g_as + s * 4;
            w0 = __expf(lrelu(as[0] + ad0));
            w1 = __expf(lrelu(as[1] + ad1));
            w2 = __expf(lrelu(as[2] + ad2));
            w3 = __expf(lrelu(as[3] + ad3));
            wsm[wid][lane][0] = w0;
            wsm[wid][lane][1] = w1;
            wsm[wid][lane][2] = w2;
            wsm[wid][lane][3] = w3;
        }
        dn0 += w0; dn1 += w1; dn2 += w2; dn3 += w3;
        __syncwarp();
        int m = min(32, row1 - base);
        for (int i = 0; i < m; i++) {
            int   s  = ssm[wid][i];
            float wt = wsm[wid][i][head];
            uint4 p = *(const uint4*)(g_hph + (size_t)s * GDIM + lane * 8);
            float2 f0 = __half22float2(*(__half2*)&p.x);
            float2 f1 = __half22float2(*(__half2*)&p.y);
            float2 f2 = __half22float2(*(__half2*)&p.z);
            float2 f3 = __half22float2(*(__half2*)&p.w);
            a0 = fmaf(f0.x, wt, a0); a1 = fmaf(f0.y, wt, a1);
            a2 = fmaf(f1.x, wt, a2); a3 = fmaf(f1.y, wt, a3);
            a4 = fmaf(f2.x, wt, a4); a5 = fmaf(f2.y, wt, a5);
            a6 = fmaf(f3.x, wt, a6); a7 = fmaf(f3.y, wt, a7);
        }
        __syncwarp();
    }
    for (int o = 16; o; o >>= 1) {
        dn0 += __shfl_xor_sync(0xffffffffu, dn0, o);
        dn1 += __shfl_xor_sync(0xffffffffu, dn1, o);
        dn2 += __shfl_xor_sync(0xffffffffu, dn2, o);
        dn3 += __shfl_xor_sync(0xffffffffu, dn3, o);
    }
    float adh = sel4(head, ad0, ad1, ad2, ad3);
    float dnh = sel4(head, dn0, dn1, dn2, dn3);

    float wslf = __expf(lrelu(g_as[d * 4 + head] + adh));
    dnh += wslf;
    {
        uint4 p = *(const uint4*)(g_hph + (size_t)d * GDIM + lane * 8);
        float2 f0 = __half22float2(*(__half2*)&p.x);
        float2 f1 = __half22float2(*(__half2*)&p.y);
        float2 f2 = __half22float2(*(__half2*)&p.z);
        float2 f3 = __half22float2(*(__half2*)&p.w);
        a0 = fmaf(f0.x, wslf, a0); a1 = fmaf(f0.y, wslf, a1);
        a2 = fmaf(f1.x, wslf, a2); a3 = fmaf(f1.y, wslf, a3);
        a4 = fmaf(f2.x, wslf, a4); a5 = fmaf(f2.y, wslf, a5);
        a6 = fmaf(f3.x, wslf, a6); a7 = fmaf(f3.y, wslf, a7);
    }
    float inv = 1.f / dnh;
    const float4* bg4 = (const float4*)(bg + lane * 8);
    float4 b0 = bg4[0], b1 = bg4[1];
    float4 o0 = make_float4(a0 * inv + b0.x, a1 * inv + b0.y,
                            a2 * inv + b0.z, a3 * inv + b0.w);
    float4 o1 = make_float4(a4 * inv + b1.x, a5 * inv + b1.y,
                            a6 * inv + b1.z, a7 * inv + b1.w);
    float4* out4 = (float4*)(outg + (size_t)d * GDIM + lane * 8);
    out4[0] = o0;
    out4[1] = o1;
}

static inline int cdiv(long long a, int b) { return (int)((a + b - 1) / b); }

static void* sym_addr(const void* sym) {
    void* p = nullptr;
    cudaGetSymbolAddress(&p, sym);
    return p;
}

extern "C" void kernel_launch(void* const* d_in, const int* in_sizes, int n_in,
                              void* d_out, int out_size) {
    const float* x       = (const float*)d_in[0];
    const int*   ei      = (const int*)  d_in[1];
    const float* W1      = (const float*)d_in[2];
    const float* b1      = (const float*)d_in[3];
    const float* W2      = (const float*)d_in[4];
    const float* b2      = (const float*)d_in[5];
    const float* Wg      = (const float*)d_in[6];
    const float* att_src = (const float*)d_in[7];
    const float* att_dst = (const float*)d_in[8];
    const float* bg      = (const float*)d_in[9];
    const float* Wf1     = (const float*)d_in[10];
    const float* bf1     = (const float*)d_in[11];
    const float* Wf2     = (const float*)d_in[12];
    const float* bf2     = (const float*)d_in[13];
    float*       out     = (float*)d_out;

    static __half* p_t64  = nullptr;
    static __half* p_hh   = nullptr;
    static float*  p_gat  = nullptr;
    static float*  p_dinv = nullptr;
    if (!p_t64) {
        p_t64  = (__half*)sym_addr(g_t64);
        p_hh   = (__half*)sym_addr(g_hh);
        p_gat  = (float*) sym_addr(g_gat);
        p_dinv = (float*) sym_addr(g_dinv);
    }

    const int B = 256;

    // ---- CSR build (gemm1 slotted at launch index 3 for profiling) ----
    k_prep<<<cdiv(NN, B), B>>>(ei);
    k_convert<<<cdiv(EE, B), B>>>(ei);
    k_dinv<<<cdiv(NN, B), B>>>();
    k_gemm1<<<cdiv(NN, 64), B>>>(x, W1, p_dinv, p_t64);  // index 3 (profiled)
    k_scan1<<<SCAN_B, B>>>();
    k_scan2<<<1, B>>>();
    k_scan3<<<cdiv(NN, B), B>>>();
    k_scatter<<<cdiv(EE, B), B>>>();

    // ---- GCN layer 1 (fp16 out) ----
    k_gcn_csr<<<cdiv(NN, 8), B>>>(p_t64, b1, p_hh);

    // ---- GCN layer 2 (fp16 in/out) ----
    k_gemm2<<<cdiv(NN, 64), B>>>(p_hh, W2, p_dinv, p_t64);
    k_gcn_csr<<<cdiv(NN, 8), B>>>(p_t64, b2, p_hh);

    // ---- GAT ----
    k_gemm_gat<<<cdiv(NN, 32), B>>>(p_hh, Wg, att_src, att_dst);
    k_gat_csr<<<cdiv(NN, 8), B>>>(bg, p_gat);

    // ---- FF head (fused Wf1+relu+Wf2) ----
    k_gemm_head<<<cdiv(NN, 64), B>>>(p_gat, Wf1, bf1, Wf2, bf2, out);

    (void)in_sizes; (void)n_in; (void)out_size;
}